// round 5
// baseline (speedup 1.0000x reference)
#include <cuda_runtime.h>
#include <math.h>
#include <stdint.h>

// ---------------- problem constants ----------------
#define NL    6
#define DMODEL 768
#define NH    12
#define DFF_  3072
#define BB    8
#define TLEN_ 512
#define SLEN_ 512
#define DH_   64
#define BT_   (BB*TLEN_)   // 4096 target tokens
#define BS_   (BB*SLEN_)   // 4096 source tokens

// ---------------- scratch (device globals: allocation-free) ----------------
__device__ float g_res [BT_*DMODEL];
__device__ float g_res2[BT_*DMODEL];
__device__ float g_lnb [BT_*DMODEL];
__device__ float g_qkv [BT_*3*DMODEL];
__device__ float g_kv  [BS_*2*DMODEL];
__device__ float g_ctx [BT_*DMODEL];
__device__ float g_ff  [BT_*DFF_];
// tf32 pre-rounded weights / memory
__device__ float g_wsa[(size_t)NL*4*DMODEL*DMODEL];
__device__ float g_wca[(size_t)NL*4*DMODEL*DMODEL];
__device__ float g_w1 [(size_t)NL*DFF_*DMODEL];
__device__ float g_w2 [(size_t)NL*DMODEL*DFF_];
__device__ float g_mem[(size_t)BS_*DMODEL];

// ---------------- TF32 helpers ----------------
__device__ __forceinline__ float to_tf32(float x)
{
    float r;
    asm("cvt.rna.tf32.f32 %0, %1;" : "=f"(r) : "f"(x));
    return r;
}

__device__ __forceinline__ void mma_tf32(float c[4], const uint32_t a[4], const uint32_t b[2])
{
    asm volatile(
        "mma.sync.aligned.m16n8k8.row.col.f32.tf32.tf32.f32 "
        "{%0,%1,%2,%3}, {%4,%5,%6,%7}, {%8,%9}, {%0,%1,%2,%3};"
        : "+f"(c[0]), "+f"(c[1]), "+f"(c[2]), "+f"(c[3])
        : "r"(a[0]), "r"(a[1]), "r"(a[2]), "r"(a[3]), "r"(b[0]), "r"(b[1]));
}

__device__ __forceinline__ void cp16(float* dst, const float* src)
{
    uint32_t s = (uint32_t)__cvta_generic_to_shared(dst);
    asm volatile("cp.async.cg.shared.global [%0], [%1], 16;" :: "r"(s), "l"(src));
}

// ---------------- fused pre-round kernel (one launch, all 5 tensors) ----------------
__global__ void round_all_kernel(const float4* __restrict__ sa, const float4* __restrict__ ca,
                                 const float4* __restrict__ f1, const float4* __restrict__ f2,
                                 const float4* __restrict__ mm,
                                 float4* __restrict__ osa, float4* __restrict__ oca,
                                 float4* __restrict__ of1, float4* __restrict__ of2,
                                 float4* __restrict__ omm)
{
    const size_t NW = (size_t)NL*4*DMODEL*DMODEL/4;
    const size_t NF = (size_t)NL*DFF_*DMODEL/4;
    const size_t NM = (size_t)BS_*DMODEL/4;
    size_t i = (size_t)blockIdx.x*256 + threadIdx.x;
    const float4* src; float4* dst; size_t off;
    if      (i < NW)            { src = sa; dst = osa; off = i; }
    else if (i < 2*NW)          { src = ca; dst = oca; off = i - NW; }
    else if (i < 2*NW + NF)     { src = f1; dst = of1; off = i - 2*NW; }
    else if (i < 2*NW + 2*NF)   { src = f2; dst = of2; off = i - 2*NW - NF; }
    else if (i < 2*NW + 2*NF + NM) { src = mm; dst = omm; off = i - 2*NW - 2*NF; }
    else return;
    float4 v = src[off];
    v.x = to_tf32(v.x); v.y = to_tf32(v.y);
    v.z = to_tf32(v.z); v.w = to_tf32(v.w);
    dst[off] = v;
}

// ---------------- embedding + positional encoding ----------------
__global__ void embed_kernel(const int* __restrict__ tgt,
                             const float* __restrict__ emb,
                             float* __restrict__ out)
{
    int row = blockIdx.x;              // b*T + t
    int t   = row & (TLEN_ - 1);
    int tok = tgt[row];
    const float* e = emb + (size_t)tok * DMODEL;
    const float c = (float)(-9.210340371976184 / (double)DMODEL);  // -ln(10000)/D
    for (int d = threadIdx.x; d < DMODEL; d += blockDim.x) {
        int k2 = d & ~1;                              // 2*i
        float div = expf((float)k2 * c);
        float ang = (float)t * div;
        float pe  = (d & 1) ? cosf(ang) : sinf(ang);
        out[(size_t)row*DMODEL + d] = e[d] * 27.712812921102035f + pe; // sqrt(768)
    }
}

// ---------------- layernorm ----------------
__device__ __forceinline__ float blockReduceSum(float v)
{
    __shared__ float sh[9];
    int lane = threadIdx.x & 31, w = threadIdx.x >> 5;
    #pragma unroll
    for (int o = 16; o; o >>= 1) v += __shfl_xor_sync(0xffffffffu, v, o);
    __syncthreads();
    if (lane == 0) sh[w] = v;
    __syncthreads();
    if (threadIdx.x == 0) {
        float t = 0.f;
        #pragma unroll
        for (int i = 0; i < 8; i++) t += sh[i];
        sh[8] = t;
    }
    __syncthreads();
    return sh[8];
}

template<bool ROUND>
__global__ __launch_bounds__(256) void ln_kernel(const float* __restrict__ X,
                                                 const float* __restrict__ gam,
                                                 const float* __restrict__ bet,
                                                 float* __restrict__ Y)
{
    int row = blockIdx.x;
    const float* x = X + (size_t)row * DMODEL;
    float s = 0.f;
    for (int d = threadIdx.x; d < DMODEL; d += 256) s += x[d];
    s = blockReduceSum(s);
    float mean = s / (float)DMODEL;
    float v = 0.f;
    for (int d = threadIdx.x; d < DMODEL; d += 256) { float t = x[d] - mean; v += t * t; }
    v = blockReduceSum(v);
    float inv = rsqrtf(v / (float)DMODEL + 1e-6f);
    for (int d = threadIdx.x; d < DMODEL; d += 256) {
        float y = (x[d] - mean) * inv * gam[d] + bet[d];
        Y[(size_t)row*DMODEL + d] = ROUND ? to_tf32(y) : y;
    }
}

// ---------------- TF32 tensor-core GEMM (3-stage cp.async, 1 sync/iter) ----------------
// C[M,N] = A[M,K] @ W[N,K]^T (+bias)(+gelu)(+round)(+resid)
// 128x128 block tile, BK=32, 256 threads = 8 warps, warp tile 32x64.
// Inputs must be pre-rounded to tf32 (mma truncation is then exact).

#define GST 36                    // smem row stride (floats), conflict-free
#define GSTAGE (2*128*GST)        // floats per stage (As+Bs)
#define GEMM_SMEM (3*GSTAGE*4)    // 110592 bytes -> 2 blocks/SM (221KB < 228KB)

template<bool BIAS, bool RESID, bool GELU, bool ROUND>
__global__ __launch_bounds__(256, 2) void gemm_tc(
    const float* __restrict__ A, const float* __restrict__ W,
    const float* __restrict__ bias, const float* __restrict__ Rm,
    float* __restrict__ C, int M, int N, int K)
{
    extern __shared__ float sh[];

    const int tid  = threadIdx.x;
    const int warp = tid >> 5, lane = tid & 31;
    const int gid  = lane >> 2, tig = lane & 3;
    const int brow = blockIdx.y * 128, bcol = blockIdx.x * 128;
    const int wr   = (warp >> 1) * 32;   // warp row offset (0,32,64,96)
    const int wc   = (warp & 1) * 64;    // warp col offset (0,64)

    const int grow = tid >> 1;           // 0..127
    const int gk   = (tid & 1) * 16;     // 0 or 16
    const float* Ap = A + (size_t)(brow + grow) * K + gk;
    const float* Wp = W + (size_t)(bcol + grow) * K + gk;
    const int soff = grow*GST + gk;

    float acc[2][8][4];
    #pragma unroll
    for (int mt = 0; mt < 2; mt++)
        #pragma unroll
        for (int nt = 0; nt < 8; nt++)
            #pragma unroll
            for (int r = 0; r < 4; r++) acc[mt][nt][r] = 0.f;

    const int niter = K >> 5;    // >= 24 for all our shapes

    // prologue: stage 0 and 1 in flight
    #pragma unroll
    for (int s = 0; s < 2; s++) {
        float* as = sh + s*GSTAGE + soff;
        float* bs = as + 128*GST;
        const float* a = Ap + s*32;
        const float* w = Wp + s*32;
        #pragma unroll
        for (int j = 0; j < 4; j++) { cp16(as + j*4, a + j*4); cp16(bs + j*4, w + j*4); }
        asm volatile("cp.async.commit_group;");
    }

    for (int it = 0; it < niter; it++) {
        if (it == niter - 1) asm volatile("cp.async.wait_group 0;");
        else                 asm volatile("cp.async.wait_group 1;");
        __syncthreads();     // stage it ready; all warps done with stage it-1

        if (it + 2 < niter) {
            const int s = (it + 2) % 3;      // == (it-1)%3, safe after the barrier
            float* as = sh + s*GSTAGE + soff;
            float* bs = as + 128*GST;
            const float* a = Ap + (it+2)*32;
            const float* w = Wp + (it+2)*32;
            #pragma unroll
            for (int j = 0; j < 4; j++) { cp16(as + j*4, a + j*4); cp16(bs + j*4, w + j*4); }
            asm volatile("cp.async.commit_group;");
        }

        const float* as = sh + (it % 3)*GSTAGE;
        const float* bs = as + 128*GST;
        #pragma unroll
        for (int ks = 0; ks < 4; ks++) {
            const int kb = ks * 8;
            uint32_t afr[2][4];
            #pragma unroll
            for (int mt = 0; mt < 2; mt++) {
                int r0 = wr + mt*16 + gid;
                afr[mt][0] = __float_as_uint(as[(r0    )*GST + kb + tig    ]);
                afr[mt][1] = __float_as_uint(as[(r0 + 8)*GST + kb + tig    ]);
                afr[mt][2] = __float_as_uint(as[(r0    )*GST + kb + tig + 4]);
                afr[mt][3] = __float_as_uint(as[(r0 + 8)*GST + kb + tig + 4]);
            }
            #pragma unroll
            for (int nt = 0; nt < 8; nt++) {
                int c0 = wc + nt*8 + gid;
                uint32_t bfr[2];
                bfr[0] = __float_as_uint(bs[c0*GST + kb + tig    ]);
                bfr[1] = __float_as_uint(bs[c0*GST + kb + tig + 4]);
                mma_tf32(acc[0][nt], afr[0], bfr);
                mma_tf32(acc[1][nt], afr[1], bfr);
            }
        }
    }

    #pragma unroll
    for (int mt = 0; mt < 2; mt++) {
        #pragma unroll
        for (int half = 0; half < 2; half++) {
            int row = brow + wr + mt*16 + gid + half*8;
            #pragma unroll
            for (int nt = 0; nt < 8; nt++) {
                int col = bcol + wc + nt*8 + 2*tig;
                float v0 = acc[mt][nt][half*2 + 0];
                float v1 = acc[mt][nt][half*2 + 1];
                if (BIAS) { v0 += bias[col]; v1 += bias[col+1]; }
                if (GELU) {
                    float u0 = v0, u1 = v1;
                    v0 = 0.5f*u0*(1.f + tanhf(0.7978845608028654f*(u0 + 0.044715f*u0*u0*u0)));
                    v1 = 0.5f*u1*(1.f + tanhf(0.7978845608028654f*(u1 + 0.044715f*u1*u1*u1)));
                }
                if (ROUND) { v0 = to_tf32(v0); v1 = to_tf32(v1); }
                if (RESID) {
                    v0 += Rm[(size_t)row*N + col];
                    v1 += Rm[(size_t)row*N + col + 1];
                }
                *(float2*)&C[(size_t)row*N + col] = make_float2(v0, v1);
            }
        }
    }
}

// ---------------- tensor-core flash attention (TF32 mma) ----------------
// 128 threads = 4 warps. q tile 64 rows (16 per warp), k tile 64, DH=64.
#define ASTQ 68
#define ASTV 72
#define ATTN_SMEM ((2*64*ASTQ + 64*ASTV)*4)

template<bool CAUSAL>
__global__ __launch_bounds__(128) void attn_tc(
    const float* __restrict__ Q, int qstride,
    const float* __restrict__ Kp, int kstride,
    const float* __restrict__ Vp, int vstride,
    const int*  __restrict__ tok, int klen,
    float* __restrict__ O, int ostride)
{
    extern __shared__ float sm[];
    float* qs = sm;                    // [64][ASTQ]
    float* ps = sm + 64*ASTQ;          // [64][ASTQ]   K tile, reused for P
    float* vs = sm + 2*64*ASTQ;        // [64][ASTV]
    __shared__ int smask[64];

    const int tid  = threadIdx.x;
    const int warp = tid >> 5, lane = tid & 31;
    const int gid  = lane >> 2, tig = lane & 3;
    const int wrow = warp * 16;
    const int qt = blockIdx.x, h = blockIdx.y, b = blockIdx.z;
    const int qbase = qt * 64;

    // load Q tile (scaled, tf32)
    {
        int lr = tid >> 1;
        int lc = (tid & 1) * 32;
        const float* qp = Q + (size_t)(b*TLEN_ + qbase + lr)*qstride + h*DH_ + lc;
        #pragma unroll
        for (int j = 0; j < 8; j++) {
            float4 v = *(const float4*)(qp + j*4);
            float* d = qs + lr*ASTQ + lc + j*4;
            d[0] = to_tf32(v.x*0.125f); d[1] = to_tf32(v.y*0.125f);
            d[2] = to_tf32(v.z*0.125f); d[3] = to_tf32(v.w*0.125f);
        }
    }

    float m[2] = {-INFINITY, -INFINITY};
    float l[2] = {0.f, 0.f};
    float oacc[8][4];
    #pragma unroll
    for (int nt = 0; nt < 8; nt++)
        #pragma unroll
        for (int r = 0; r < 4; r++) oacc[nt][r] = 0.f;

    const int nkt = CAUSAL ? (qt + 1) : (klen >> 6);
    for (int kt = 0; kt < nkt; kt++) {
        __syncthreads();
        {
            int lr = tid >> 1;
            int lc = (tid & 1) * 32;
            const float* kp = Kp + (size_t)(b*klen + kt*64 + lr)*kstride + h*DH_ + lc;
            const float* vp = Vp + (size_t)(b*klen + kt*64 + lr)*vstride + h*DH_ + lc;
            #pragma unroll
            for (int j = 0; j < 8; j++) {
                float4 kv4 = *(const float4*)(kp + j*4);
                float* dk = ps + lr*ASTQ + lc + j*4;
                dk[0] = to_tf32(kv4.x); dk[1] = to_tf32(kv4.y);
                dk[2] = to_tf32(kv4.z); dk[3] = to_tf32(kv4.w);
                float4 vv4 = *(const float4*)(vp + j*4);
                float* dv = vs + lr*ASTV + lc + j*4;
                dv[0] = to_tf32(vv4.x); dv[1] = to_tf32(vv4.y);
                dv[2] = to_tf32(vv4.z); dv[3] = to_tf32(vv4.w);
            }
            if (tid < 64) smask[tid] = (tok[b*klen + kt*64 + tid] == 0);
        }
        __syncthreads();

        // ---- S = Q @ K^T
        float sfr[8][4];
        #pragma unroll
        for (int nt = 0; nt < 8; nt++)
            #pragma unroll
            for (int r = 0; r < 4; r++) sfr[nt][r] = 0.f;

        #pragma unroll
        for (int ks8 = 0; ks8 < 8; ks8++) {
            const int kb = ks8*8;
            uint32_t a[4];
            a[0] = __float_as_uint(qs[(wrow+gid  )*ASTQ + kb + tig    ]);
            a[1] = __float_as_uint(qs[(wrow+gid+8)*ASTQ + kb + tig    ]);
            a[2] = __float_as_uint(qs[(wrow+gid  )*ASTQ + kb + tig + 4]);
            a[3] = __float_as_uint(qs[(wrow+gid+8)*ASTQ + kb + tig + 4]);
            #pragma unroll
            for (int nt = 0; nt < 8; nt++) {
                uint32_t bf[2];
                bf[0] = __float_as_uint(ps[(nt*8+gid)*ASTQ + kb + tig    ]);
                bf[1] = __float_as_uint(ps[(nt*8+gid)*ASTQ + kb + tig + 4]);
                mma_tf32(sfr[nt], a, bf);
            }
        }

        // ---- mask (replace with -1e18, matching reference)
        #pragma unroll
        for (int nt = 0; nt < 8; nt++) {
            #pragma unroll
            for (int e = 0; e < 4; e++) {
                int cl = nt*8 + 2*tig + (e & 1);
                int rowg = qbase + wrow + gid + (e >> 1)*8;
                int colg = kt*64 + cl;
                bool msk = (smask[cl] != 0) || (CAUSAL && colg > rowg);
                if (msk) sfr[nt][e] = -1e18f;
            }
        }

        // ---- online softmax
        #pragma unroll
        for (int h2 = 0; h2 < 2; h2++) {
            float rm = -INFINITY;
            #pragma unroll
            for (int nt = 0; nt < 8; nt++)
                rm = fmaxf(rm, fmaxf(sfr[nt][h2*2], sfr[nt][h2*2+1]));
            rm = fmaxf(rm, __shfl_xor_sync(0xffffffffu, rm, 1));
            rm = fmaxf(rm, __shfl_xor_sync(0xffffffffu, rm, 2));
            float nm = fmaxf(m[h2], rm);
            float alpha = __expf(m[h2] - nm);
            float rs = 0.f;
            #pragma unroll
            for (int nt = 0; nt < 8; nt++) {
                float p0 = __expf(sfr[nt][h2*2]   - nm);
                float p1 = __expf(sfr[nt][h2*2+1] - nm);
                sfr[nt][h2*2] = p0; sfr[nt][h2*2+1] = p1;
                rs += p0 + p1;
            }
            rs += __shfl_xor_sync(0xffffffffu, rs, 1);
            rs += __shfl_xor_sync(0xffffffffu, rs, 2);
            l[h2] = l[h2]*alpha + rs;
            m[h2] = nm;
            #pragma unroll
            for (int nt = 0; nt < 8; nt++) {
                oacc[nt][h2*2]   *= alpha;
                oacc[nt][h2*2+1] *= alpha;
            }
        }

        __syncthreads();

        // ---- write P (tf32) into ps
        #pragma unroll
        for (int nt = 0; nt < 8; nt++) {
            #pragma unroll
            for (int h2 = 0; h2 < 2; h2++) {
                float* d = ps + (wrow + gid + h2*8)*ASTQ + nt*8 + 2*tig;
                d[0] = to_tf32(sfr[nt][h2*2]);
                d[1] = to_tf32(sfr[nt][h2*2+1]);
            }
        }
        __syncwarp();

        // ---- O += P @ V
        #pragma unroll
        for (int ks8 = 0; ks8 < 8; ks8++) {
            const int kb = ks8*8;
            uint32_t a[4];
            a[0] = __float_as_uint(ps[(wrow+gid  )*ASTQ + kb + tig    ]);
            a[1] = __float_as_uint(ps[(wrow+gid+8)*ASTQ + kb + tig    ]);
            a[2] = __float_as_uint(ps[(wrow+gid  )*ASTQ + kb + tig + 4]);
            a[3] = __float_as_uint(ps[(wrow+gid+8)*ASTQ + kb + tig + 4]);
            #pragma unroll
            for (int nt = 0; nt < 8; nt++) {
                uint32_t bf[2];
                bf[0] = __float_as_uint(vs[(kb+tig  )*ASTV + nt*8 + gid]);
                bf[1] = __float_as_uint(vs[(kb+tig+4)*ASTV + nt*8 + gid]);
                mma_tf32(oacc[nt], a, bf);
            }
        }
    }

    // ---- epilogue: O = tf32(acc / l)  (ctx feeds GEMM A-input)
    float inv0 = 1.f / l[0];
    float inv1 = 1.f / l[1];
    size_t r0 = (size_t)(b*TLEN_ + qbase + wrow + gid)*ostride + h*DH_;
    size_t r1 = r0 + (size_t)8*ostride;
    #pragma unroll
    for (int nt = 0; nt < 8; nt++) {
        int col = nt*8 + 2*tig;
        *(float2*)&O[r0 + col] = make_float2(to_tf32(oacc[nt][0]*inv0), to_tf32(oacc[nt][1]*inv0));
        *(float2*)&O[r1 + col] = make_float2(to_tf32(oacc[nt][2]*inv1), to_tf32(oacc[nt][3]*inv1));
    }
}

// ---------------- host orchestration ----------------
extern "C" void kernel_launch(void* const* d_in, const int* in_sizes, int n_in,
                              void* d_out, int out_size)
{
    (void)in_sizes; (void)n_in; (void)out_size;
    const int*   tgt    = (const int*)  d_in[0];
    const int*   src    = (const int*)  d_in[1];
    const float* memory = (const float*)d_in[2];
    const float* emb    = (const float*)d_in[3];
    const float* sa_w   = (const float*)d_in[4];
    const float* sa_b   = (const float*)d_in[5];
    const float* ca_w   = (const float*)d_in[6];
    const float* ca_b   = (const float*)d_in[7];
    const float* ln_g   = (const float*)d_in[8];
    const float* ln_b   = (const float*)d_in[9];
    const float* ff_w1  = (const float*)d_in[10];
    const float* ff_b1  = (const float*)d_in[11];
    const float* ff_w2  = (const float*)d_in[12];
    const float* ff_b2  = (const float*)d_in[13];
    const float* out_g  = (const float*)d_in[14];
    const float* out_b  = (const float*)d_in[15];
    float* out = (float*)d_out;

    float *res, *res2, *lnb, *qkv, *kv, *ctx, *ff;
    float *wsa, *wca, *w1, *w2, *mem;
    cudaGetSymbolAddress((void**)&res,  g_res);
    cudaGetSymbolAddress((void**)&res2, g_res2);
    cudaGetSymbolAddress((void**)&lnb,  g_lnb);
    cudaGetSymbolAddress((void**)&qkv,  g_qkv);
    cudaGetSymbolAddress((void**)&kv,   g_kv);
    cudaGetSymbolAddress((void**)&ctx,  g_ctx);
    cudaGetSymbolAddress((void**)&ff,   g_ff);
    cudaGetSymbolAddress((void**)&wsa,  g_wsa);
    cudaGetSymbolAddress((void**)&wca,  g_wca);
    cudaGetSymbolAddress((void**)&w1,   g_w1);
    cudaGetSymbolAddress((void**)&w2,   g_w2);
    cudaGetSymbolAddress((void**)&mem,  g_mem);

    cudaFuncSetAttribute(attn_tc<true>,  cudaFuncAttributeMaxDynamicSharedMemorySize, ATTN_SMEM);
    cudaFuncSetAttribute(attn_tc<false>, cudaFuncAttributeMaxDynamicSharedMemorySize, ATTN_SMEM);
    cudaFuncSetAttribute((gemm_tc<true,false,false,false>), cudaFuncAttributeMaxDynamicSharedMemorySize, GEMM_SMEM);
    cudaFuncSetAttribute((gemm_tc<true,true ,false,false>), cudaFuncAttributeMaxDynamicSharedMemorySize, GEMM_SMEM);
    cudaFuncSetAttribute((gemm_tc<true,false,true ,true >), cudaFuncAttributeMaxDynamicSharedMemorySize, GEMM_SMEM);

    // #1 embed, #2 fused tf32 pre-round  (so launch #6 = attn-out GEMM for ncu)
    embed_kernel<<<BT_, 256>>>(tgt, emb, res);
    {
        const size_t NW = (size_t)NL*4*DMODEL*DMODEL/4;
        const size_t NF = (size_t)NL*DFF_*DMODEL/4;
        const size_t NM = (size_t)BS_*DMODEL/4;
        const size_t total = 2*NW + 2*NF + NM;
        round_all_kernel<<<(unsigned)((total + 255)/256), 256>>>(
            (const float4*)sa_w, (const float4*)ca_w,
            (const float4*)ff_w1, (const float4*)ff_w2, (const float4*)memory,
            (float4*)wsa, (float4*)wca, (float4*)w1, (float4*)w2, (float4*)mem);
    }

    const dim3 g768 (DMODEL/128, BT_/128);
    const dim3 g1536(2*DMODEL/128, BS_/128);
    const dim3 g2304(3*DMODEL/128, BT_/128);
    const dim3 g3072(DFF_/128, BT_/128);
    const dim3 attn_grid(TLEN_/64, NH, BB);

    for (int i = 0; i < NL; i++) {
        const float* saw = wsa + (size_t)i*4*DMODEL*DMODEL;
        const float* sab = sa_b + (size_t)i*4*DMODEL;
        const float* caw = wca + (size_t)i*4*DMODEL*DMODEL;
        const float* cab = ca_b + (size_t)i*4*DMODEL;
        const float* lg  = ln_g + (size_t)i*3*DMODEL;
        const float* lb  = ln_b + (size_t)i*3*DMODEL;

        // ----- self attention -----
        ln_kernel<true><<<BT_, 256>>>(res, lg, lb, lnb);
        gemm_tc<true,false,false,false><<<g2304, 256, GEMM_SMEM>>>(lnb, saw, sab, nullptr, qkv,
                                                  BT_, 3*DMODEL, DMODEL);
        attn_tc<true><<<attn_grid, 128, ATTN_SMEM>>>(
            qkv, 3*DMODEL, qkv + DMODEL, 3*DMODEL, qkv + 2*DMODEL, 3*DMODEL,
            tgt, TLEN_, ctx, DMODEL);
        gemm_tc<true,true,false,false><<<g768, 256, GEMM_SMEM>>>(ctx, saw + (size_t)3*DMODEL*DMODEL,
                                                sab + 3*DMODEL, res, res2,
                                                BT_, DMODEL, DMODEL);

        // ----- cross attention -----
        ln_kernel<true><<<BT_, 256>>>(res2, lg + DMODEL, lb + DMODEL, lnb);
        gemm_tc<true,false,false,false><<<g768, 256, GEMM_SMEM>>>(lnb, caw, cab, nullptr, qkv,
                                                 BT_, DMODEL, DMODEL);
        gemm_tc<true,false,false,false><<<g1536, 256, GEMM_SMEM>>>(mem, caw + (size_t)DMODEL*DMODEL,
                                                  cab + DMODEL, nullptr, kv,
                                                  BS_, 2*DMODEL, DMODEL);
        attn_tc<false><<<attn_grid, 128, ATTN_SMEM>>>(
            qkv, DMODEL, kv, 2*DMODEL, kv + DMODEL, 2*DMODEL,
            src, SLEN_, ctx, DMODEL);
        gemm_tc<true,true,false,false><<<g768, 256, GEMM_SMEM>>>(ctx, caw + (size_t)3*DMODEL*DMODEL,
                                                cab + 3*DMODEL, res2, res,
                                                BT_, DMODEL, DMODEL);

        // ----- FFN -----
        ln_kernel<true><<<BT_, 256>>>(res, lg + 2*DMODEL, lb + 2*DMODEL, lnb);
        gemm_tc<true,false,true,true><<<g3072, 256, GEMM_SMEM>>>(lnb, w1 + (size_t)i*DFF_*DMODEL,
                                                 ff_b1 + (size_t)i*DFF_, nullptr, ff,
                                                 BT_, DFF_, DMODEL);
        gemm_tc<true,true,false,false><<<g768, 256, GEMM_SMEM>>>(ff, w2 + (size_t)i*DMODEL*DFF_,
                                                ff_b2 + (size_t)i*DMODEL, res, res2,
                                                BT_, DMODEL, DFF_);

        float* tmp = res; res = res2; res2 = tmp;
    }

    ln_kernel<false><<<BT_, 256>>>(res, out_g, out_b, out);
}